// round 10
// baseline (speedup 1.0000x reference)
#include <cuda_runtime.h>
#include <cuda_fp16.h>
#include <cstdint>

#define NMAX 100000
#define EMAX 1600000
#define ETOT (EMAX + NMAX)
#define SCAN_CHUNK 1024
#define NBMAX ((NMAX + SCAN_CHUNK - 1) / SCAN_CHUNK)
#define HIST_BLOCKS 1184

// ---------------------------------------------------------------------------
// Static scratch (zero-initialized at module load; kernels restore the
// zero-invariants they rely on so CUDA-graph replays stay deterministic).
// ---------------------------------------------------------------------------
__device__ __half g_h1h[NMAX * 64];  // x @ W1   (fp16 storage, fp32 accum)
__device__ float  g_o1[NMAX * 64];   // relu(aggregate layer1) = input to GEMM2
__device__ float  g_h2[NMAX * 32];   // o1 @ W2
__device__ float  g_as1[NMAX], g_ad1[NMAX];
__device__ float  g_as2[NMAX], g_ad2[NMAX];
__device__ int    g_deg[NMAX];       // invariant: zero at kernel_launch entry
__device__ int    g_off[NMAX + 1];
__device__ int    g_cur[NMAX];
__device__ int    g_csr[ETOT];       // src ids (layer-2 gather)
__device__ float2 g_csre[ETOT];      // (as1[src], h1-row offset) per edge
__device__ unsigned long long g_scan[NBMAX];  // invariant: zero at entry
__device__ int    g_scan_done;                // invariant: zero at entry

// ---------------------------------------------------------------------------
// Fused scan + scatter. Blocks 0..nb-1: decoupled-lookback exclusive scan of
// (deg+1), zeroing g_deg. Blocks >= nb: spin until all scan blocks publish
// (fence + done-counter; scan blocks are wave-1 by bid order, no deadlock),
// then scatter src ids + (as1, offset) pairs into CSR slots.
// ---------------------------------------------------------------------------
__global__ void __launch_bounds__(256) scan_scatter_kernel(
    const int* __restrict__ ei, int e, int n, int nb)
{
    const int b = blockIdx.x;
    if (b < nb) {
        __shared__ int sm[256];
        __shared__ int s_excl;
        const int t = threadIdx.x;
        const int i0 = b * SCAN_CHUNK + t * 4;

        int v[4];
        int s = 0;
#pragma unroll
        for (int u = 0; u < 4; ++u) {
            int i = i0 + u;
            if (i < n) {
                v[u] = g_deg[i] + 1;   // +1 self-loop folded in
                g_deg[i] = 0;          // restore invariant
            } else v[u] = 0;
            s += v[u];
        }
        sm[t] = s;
        __syncthreads();
        for (int st = 1; st < 256; st <<= 1) {
            int a = (t >= st) ? sm[t - st] : 0;
            __syncthreads();
            sm[t] += a;
            __syncthreads();
        }
        const int incl = sm[t];
        const int total = sm[255];

        if (t == 0) {
            unsigned long long pub = ((b == 0) ? (2ULL << 32) : (1ULL << 32)) |
                                     (unsigned int)total;
            atomicExch(&g_scan[b], pub);
            int excl = 0;
            if (b > 0) {
                int j = b - 1;
                for (;;) {
                    unsigned long long st2;
                    do {
                        st2 = atomicAdd(&g_scan[j], 0ULL);
                        if (!(st2 >> 32)) __nanosleep(40);
                    } while (!(st2 >> 32));
                    excl += (int)(unsigned int)st2;
                    if ((st2 >> 32) == 2ULL) break;
                    --j;
                }
                atomicExch(&g_scan[b], (2ULL << 32) | (unsigned int)(excl + total));
            }
            s_excl = excl;
        }
        __syncthreads();

        int pref = s_excl + (incl - s);
#pragma unroll
        for (int u = 0; u < 4; ++u) {
            int i = i0 + u;
            if (i < n) { g_off[i] = pref; g_cur[i] = pref; }
            pref += v[u];
        }
        if (b == nb - 1 && t == 255) g_off[n] = s_excl + total;

        __threadfence();    // publish this thread's g_off/g_cur device-wide
        __syncthreads();
        if (t == 0) atomicAdd(&g_scan_done, 1);
    } else {
        // ---- scatter part ----
        if (threadIdx.x == 0) {
            while (atomicAdd(&g_scan_done, 0) < nb) __nanosleep(64);
            __threadfence();
        }
        __syncthreads();
        int t = (b - nb) * 256 + threadIdx.x;
        if (t < e) {
            int src = ei[t];
            int dst = ei[e + t];
            int pos = atomicAdd(&g_cur[dst], 1);
            g_csr[pos] = src;
            g_csre[pos] = make_float2(g_as1[src], __int_as_float(src * 32));
        } else if (t < e + n) {
            int i = t - e;
            int pos = atomicAdd(&g_cur[i], 1);
            g_csr[pos] = i;              // self-loop
            g_csre[pos] = make_float2(g_as1[i], __int_as_float(i * 32));
        }
    }
}

// ---------------------------------------------------------------------------
// Tensor-core GEMM (HMMA m16n8k16, fp16 in / fp32 accum) + fused alpha
// (unchanged from R8).
// ---------------------------------------------------------------------------
__device__ __forceinline__ void ldsm_x4(uint32_t a[4], uint32_t addr) {
    asm volatile("ldmatrix.sync.aligned.m8n8.x4.shared.b16 {%0,%1,%2,%3},[%4];"
                 : "=r"(a[0]), "=r"(a[1]), "=r"(a[2]), "=r"(a[3]) : "r"(addr));
}
__device__ __forceinline__ void ldsm_x4_t(uint32_t a[4], uint32_t addr) {
    asm volatile("ldmatrix.sync.aligned.m8n8.x4.trans.shared.b16 {%0,%1,%2,%3},[%4];"
                 : "=r"(a[0]), "=r"(a[1]), "=r"(a[2]), "=r"(a[3]) : "r"(addr));
}
__device__ __forceinline__ void mma16816(float c[4], const uint32_t a[4],
                                         const uint32_t* b) {
    asm volatile(
        "mma.sync.aligned.m16n8k16.row.col.f32.f16.f16.f32 "
        "{%0,%1,%2,%3},{%4,%5,%6,%7},{%8,%9},{%0,%1,%2,%3};"
        : "+f"(c[0]), "+f"(c[1]), "+f"(c[2]), "+f"(c[3])
        : "r"(a[0]), "r"(a[1]), "r"(a[2]), "r"(a[3]), "r"(b[0]), "r"(b[1]));
}

template <int K, int M, typename TH>
__device__ __forceinline__ void gemm_mma_body(
    const float* __restrict__ X, const float* __restrict__ W,
    TH* __restrict__ H,
    const float* __restrict__ a_s, const float* __restrict__ a_d,
    float* __restrict__ as_out, float* __restrict__ ad_out,
    int n, int bid)
{
    constexpr int AP = K + 8;
    constexpr int NP = M + 8;
    constexpr int NT = M / 16;
    constexpr int KS = K / 16;
    __shared__ __half As[64 * AP];
    __shared__ __half Bs[K * NP];
    __shared__ float  sAs[64], sAd[64];

    const int tid = threadIdx.x;
    const int lane = tid & 31;
    const int wid = tid >> 5;
    const int nb = bid * 64;

    if (tid < 64) { sAs[tid] = 0.f; sAd[tid] = 0.f; }

#pragma unroll
    for (int it = 0; it < K / 16; ++it) {
        int idx = tid + it * 256;
        int r = idx / (K / 4);
        int c4 = idx % (K / 4);
        int node = nb + r;
        float4 v = make_float4(0.f, 0.f, 0.f, 0.f);
        if (node < n)
            v = *reinterpret_cast<const float4*>(X + (size_t)node * K + c4 * 4);
        __half2 h0 = __floats2half2_rn(v.x, v.y);
        __half2 h1 = __floats2half2_rn(v.z, v.w);
        uint2 pk = make_uint2(*(uint32_t*)&h0, *(uint32_t*)&h1);
        *reinterpret_cast<uint2*>(&As[r * AP + c4 * 4]) = pk;
    }
#pragma unroll
    for (int it = 0; it < (K * M / 4) / 256; ++it) {
        int idx = tid + it * 256;
        int r = idx / (M / 4);
        int c4 = idx % (M / 4);
        float4 v = *reinterpret_cast<const float4*>(W + (size_t)r * M + c4 * 4);
        __half2 h0 = __floats2half2_rn(v.x, v.y);
        __half2 h1 = __floats2half2_rn(v.z, v.w);
        uint2 pk = make_uint2(*(uint32_t*)&h0, *(uint32_t*)&h1);
        *reinterpret_cast<uint2*>(&Bs[r * NP + c4 * 4]) = pk;
    }
    __syncthreads();

    const int r0 = (wid >> 1) * 16;
    const int n0 = (wid & 1) * (M == 64 ? 32 : 16);

    float c[NT][4];
#pragma unroll
    for (int t2 = 0; t2 < NT; ++t2)
#pragma unroll
        for (int u = 0; u < 4; ++u) c[t2][u] = 0.f;

    const uint32_t aBase = (uint32_t)__cvta_generic_to_shared(As);
    const uint32_t bBase = (uint32_t)__cvta_generic_to_shared(Bs);

#pragma unroll
    for (int kk = 0; kk < KS; ++kk) {
        int k0 = kk * 16;
        uint32_t a[4];
        ldsm_x4(a, aBase + ((r0 + (lane & 15)) * AP + k0 + ((lane >> 4) << 3)) * 2);
#pragma unroll
        for (int tp = 0; tp < NT / 2; ++tp) {
            int ncol = n0 + tp * 16;
            int row = k0 + ((lane >> 3) & 1) * 8 + (lane & 7);
            int col = ncol + (lane >> 4) * 8;
            uint32_t bb[4];
            ldsm_x4_t(bb, bBase + (row * NP + col) * 2);
            mma16816(c[tp * 2], a, bb);
            mma16816(c[tp * 2 + 1], a, bb + 2);
        }
    }

    const int group = lane >> 2;
    const int qt = lane & 3;
    const int rlo = r0 + group, rhi = rlo + 8;
    const int nlo = nb + rlo, nhi = nb + rhi;
    float slo = 0.f, dlo = 0.f, shi = 0.f, dhi = 0.f;
#pragma unroll
    for (int t2 = 0; t2 < NT; ++t2) {
        int c0 = n0 + t2 * 8 + qt * 2;
        float as0 = a_s[c0], as1 = a_s[c0 + 1];
        float ad0 = a_d[c0], ad1 = a_d[c0 + 1];
        slo += c[t2][0] * as0 + c[t2][1] * as1;
        dlo += c[t2][0] * ad0 + c[t2][1] * ad1;
        shi += c[t2][2] * as0 + c[t2][3] * as1;
        dhi += c[t2][2] * ad0 + c[t2][3] * ad1;
        if (nlo < n) {
            if constexpr (sizeof(TH) == 2) {
                __half2 h = __floats2half2_rn(c[t2][0], c[t2][1]);
                *reinterpret_cast<__half2*>((__half*)H + (size_t)nlo * M + c0) = h;
            } else {
                *reinterpret_cast<float2*>((float*)H + (size_t)nlo * M + c0) =
                    make_float2(c[t2][0], c[t2][1]);
            }
        }
        if (nhi < n) {
            if constexpr (sizeof(TH) == 2) {
                __half2 h = __floats2half2_rn(c[t2][2], c[t2][3]);
                *reinterpret_cast<__half2*>((__half*)H + (size_t)nhi * M + c0) = h;
            } else {
                *reinterpret_cast<float2*>((float*)H + (size_t)nhi * M + c0) =
                    make_float2(c[t2][2], c[t2][3]);
            }
        }
    }
#pragma unroll
    for (int o = 1; o <= 2; o <<= 1) {
        slo += __shfl_xor_sync(0xffffffffu, slo, o);
        dlo += __shfl_xor_sync(0xffffffffu, dlo, o);
        shi += __shfl_xor_sync(0xffffffffu, shi, o);
        dhi += __shfl_xor_sync(0xffffffffu, dhi, o);
    }
    if (qt == 0) {
        atomicAdd(&sAs[rlo], slo);
        atomicAdd(&sAd[rlo], dlo);
        atomicAdd(&sAs[rhi], shi);
        atomicAdd(&sAd[rhi], dhi);
    }
    __syncthreads();
    if (tid < 64) {
        int node = nb + tid;
        if (node < n) { as_out[node] = sAs[tid]; ad_out[node] = sAd[tid]; }
    }
}

__global__ void __launch_bounds__(256) fused_gemm1_hist_kernel(
    const float* __restrict__ X, const float* __restrict__ W1,
    const float* __restrict__ aS1, const float* __restrict__ aD1,
    const int* __restrict__ ei, int n, int e, int gemm_blocks)
{
    if ((int)blockIdx.x < gemm_blocks) {
        gemm_mma_body<128, 64, __half>(X, W1, g_h1h, aS1, aD1,
                                       g_as1, g_ad1, n, blockIdx.x);
    } else {
        int hb = gridDim.x - gemm_blocks;
        for (int t = (blockIdx.x - gemm_blocks) * 256 + threadIdx.x; t < e;
             t += hb * 256) {
            int dst = ei[e + t];
            atomicAdd(&g_deg[dst], 1);
        }
    }
}

__global__ void __launch_bounds__(256) gemm2_kernel(
    const float* __restrict__ W2,
    const float* __restrict__ aS2, const float* __restrict__ aD2, int n)
{
    gemm_mma_body<64, 32, float>(g_o1, W2, g_h2, aS2, aD2,
                                 g_as2, g_ad2, n, blockIdx.x);
}

// ---------------------------------------------------------------------------
// Gather layer 1 (R8 layout + pair-CSR): warp per node, smem-staged weights.
// Phase A: ONE coalesced LDG.64 gives (as1[src], row offset) — no dependent
// random load. Phase B: broadcast LDS.64 + per-lane half2 load, unroll 8.
// Block 0 also resets the scan-state invariants for the next graph replay.
// ---------------------------------------------------------------------------
__global__ void __launch_bounds__(256) gather64_kernel(
    const float* __restrict__ b, int n)
{
    if (blockIdx.x == 0) {
        if (threadIdx.x < NBMAX) g_scan[threadIdx.x] = 0ULL;
        if (threadIdx.x == 255) g_scan_done = 0;
    }
    __shared__ float2 stage[8][32];
    int node = (blockIdx.x * blockDim.x + threadIdx.x) >> 5;
    int lane = threadIdx.x & 31;
    int wid = (threadIdx.x >> 5) & 7;
    if (node >= n) return;
    int p0 = g_off[node], p1 = g_off[node + 1];
    float advl = g_ad1[node];
    const __half2* hb = reinterpret_cast<const __half2*>(g_h1h) + lane;
    float sum = 0.f, a0 = 0.f, a1 = 0.f;

    for (int base = p0; base < p1; base += 32) {
        int p = base + lane;
        float w = 0.f;
        float offb = 0.f;
        if (p < p1) {
            float2 pr = g_csre[p];
            float ev = pr.x + advl;
            ev = ev > 0.f ? ev : 0.2f * ev;
            w = __expf(ev);
            offb = pr.y;
        }
        sum += w;
        stage[wid][lane] = make_float2(w, offb);
        __syncwarp();
        int nc = min(32, p1 - base);
#pragma unroll 8
        for (int j = 0; j < nc; ++j) {
            float2 sj = stage[wid][j];
            float2 hv = __half22float2(hb[__float_as_int(sj.y)]);
            a0 = fmaf(sj.x, hv.x, a0);
            a1 = fmaf(sj.x, hv.y, a1);
        }
        __syncwarp();
    }
#pragma unroll
    for (int o = 16; o; o >>= 1) sum += __shfl_xor_sync(0xffffffffu, sum, o);
    float inv = 1.f / (sum + 1e-16f);
    float2 o;
    o.x = fmaxf(fmaf(a0, inv, b[lane * 2]), 0.f);
    o.y = fmaxf(fmaf(a1, inv, b[lane * 2 + 1]), 0.f);
    *reinterpret_cast<float2*>(g_o1 + (size_t)node * 64 + lane * 2) = o;
}

// ---------------------------------------------------------------------------
// Gather layer 2 + fused log_softmax (R8 layout, unroll 8).
// ---------------------------------------------------------------------------
__global__ void __launch_bounds__(256) gather32_kernel(
    const float* __restrict__ b, float* __restrict__ out, int n)
{
    __shared__ float2 stage[8][32];
    int node = (blockIdx.x * blockDim.x + threadIdx.x) >> 5;
    int lane = threadIdx.x & 31;
    int wid = (threadIdx.x >> 5) & 7;
    if (node >= n) return;
    int p0 = g_off[node], p1 = g_off[node + 1];
    float advl = g_ad2[node];
    const float* hb = g_h2 + lane;
    float sum = 0.f, acc = 0.f;

    for (int base = p0; base < p1; base += 32) {
        int p = base + lane;
        int src = 0;
        float w = 0.f;
        if (p < p1) {
            src = g_csr[p];
            float ev = g_as2[src] + advl;
            ev = ev > 0.f ? ev : 0.2f * ev;
            w = __expf(ev);
        }
        sum += w;
        stage[wid][lane] = make_float2(w, __int_as_float(src * 32));
        __syncwarp();
        int nc = min(32, p1 - base);
#pragma unroll 8
        for (int j = 0; j < nc; ++j) {
            float2 sj = stage[wid][j];
            acc = fmaf(sj.x, hb[__float_as_int(sj.y)], acc);
        }
        __syncwarp();
    }
#pragma unroll
    for (int o = 16; o; o >>= 1) sum += __shfl_xor_sync(0xffffffffu, sum, o);

    float v = fmaf(acc, 1.f / (sum + 1e-16f), b[lane]);
    float m = v;
#pragma unroll
    for (int o = 16; o; o >>= 1) m = fmaxf(m, __shfl_xor_sync(0xffffffffu, m, o));
    float ex = __expf(v - m);
    float s2 = ex;
#pragma unroll
    for (int o = 16; o; o >>= 1) s2 += __shfl_xor_sync(0xffffffffu, s2, o);
    out[(size_t)node * 32 + lane] = v - m - __logf(s2);
}

// ---------------------------------------------------------------------------
// Launch: 5 kernels, no runtime API calls.
// ---------------------------------------------------------------------------
extern "C" void kernel_launch(void* const* d_in, const int* in_sizes, int n_in,
                              void* d_out, int out_size) {
    const float* x   = (const float*)d_in[0];
    const int*   ei  = (const int*)d_in[1];     // int64 coerced to int32 by harness
    const float* W1  = (const float*)d_in[2];
    const float* aS1 = (const float*)d_in[3];
    const float* aD1 = (const float*)d_in[4];
    const float* b1  = (const float*)d_in[5];
    const float* W2  = (const float*)d_in[6];
    const float* aS2 = (const float*)d_in[7];
    const float* aD2 = (const float*)d_in[8];
    const float* b2  = (const float*)d_in[9];
    float* out = (float*)d_out;

    const int n = in_sizes[0] / 128;
    const int e = in_sizes[1] / 2;
    const int etot = e + n;
    const int nb = (n + SCAN_CHUNK - 1) / SCAN_CHUNK;
    const int gemm1_blocks = (n + 63) / 64;
    const int scat_blocks = (etot + 255) / 256;

    // [GEMM1+alpha1 | edge histogram]  (g_deg arrives zeroed: invariant)
    fused_gemm1_hist_kernel<<<gemm1_blocks + HIST_BLOCKS, 256>>>(
        x, W1, aS1, aD1, ei, n, e, gemm1_blocks);

    // fused CSR offsets + scatter (scan blocks first, scatter blocks gated)
    scan_scatter_kernel<<<nb + scat_blocks, 256>>>(ei, e, n, nb);

    // Layer 1 aggregate (+bias+ReLU); also resets scan-state invariants
    gather64_kernel<<<(n * 32 + 255) / 256, 256>>>(b1, n);

    // Layer 2
    gemm2_kernel<<<(n + 63) / 64, 256>>>(W2, aS2, aD2, n);
    gather32_kernel<<<(n * 32 + 255) / 256, 256>>>(b2, out, n);
}

// round 11
// speedup vs baseline: 1.1894x; 1.1894x over previous
#include <cuda_runtime.h>
#include <cuda_fp16.h>
#include <cstdint>

#define NMAX 100000
#define EMAX 1600000
#define ETOT (EMAX + NMAX)
#define SCAN_CHUNK 1024
#define NBMAX ((NMAX + SCAN_CHUNK - 1) / SCAN_CHUNK)
#define HIST_BLOCKS 1184

// ---------------------------------------------------------------------------
// Static scratch (zero-initialized at module load; kernels restore the
// zero-invariants they rely on so CUDA-graph replays stay deterministic).
// ---------------------------------------------------------------------------
__device__ __half g_h1h[NMAX * 64];  // x @ W1   (fp16 storage, fp32 accum)
__device__ __half g_o1h[NMAX * 64];  // relu(aggregate L1), fp16 (= GEMM2 input)
__device__ float  g_h2[NMAX * 32];   // o1 @ W2
__device__ float  g_as1[NMAX], g_ad1[NMAX];
__device__ float  g_as2[NMAX], g_ad2[NMAX];
__device__ int    g_deg[NMAX];       // invariant: zero at kernel_launch entry
__device__ int    g_off[NMAX + 1];
__device__ int    g_cur[NMAX];
__device__ int    g_csr[ETOT];
__device__ unsigned long long g_scan[NBMAX];  // invariant: zero at entry

// ---------------------------------------------------------------------------
// Single-pass exclusive scan of (deg[i]+1), decoupled lookback (as R8).
// ---------------------------------------------------------------------------
__global__ void __launch_bounds__(256) scan_onepass_kernel(int n, int nb) {
    __shared__ int sm[256];
    __shared__ int s_excl;
    const int b = blockIdx.x;
    const int t = threadIdx.x;
    const int i0 = b * SCAN_CHUNK + t * 4;

    int v[4];
    int s = 0;
#pragma unroll
    for (int u = 0; u < 4; ++u) {
        int i = i0 + u;
        if (i < n) {
            v[u] = g_deg[i] + 1;
            g_deg[i] = 0;
        } else v[u] = 0;
        s += v[u];
    }
    sm[t] = s;
    __syncthreads();
    for (int st = 1; st < 256; st <<= 1) {
        int a = (t >= st) ? sm[t - st] : 0;
        __syncthreads();
        sm[t] += a;
        __syncthreads();
    }
    const int incl = sm[t];
    const int total = sm[255];

    if (t == 0) {
        unsigned long long pub = ((b == 0) ? (2ULL << 32) : (1ULL << 32)) |
                                 (unsigned int)total;
        atomicExch(&g_scan[b], pub);
        int excl = 0;
        if (b > 0) {
            int j = b - 1;
            for (;;) {
                unsigned long long st2;
                do {
                    st2 = atomicAdd(&g_scan[j], 0ULL);
                    if (!(st2 >> 32)) __nanosleep(40);
                } while (!(st2 >> 32));
                excl += (int)(unsigned int)st2;
                if ((st2 >> 32) == 2ULL) break;
                --j;
            }
            atomicExch(&g_scan[b], (2ULL << 32) | (unsigned int)(excl + total));
        }
        s_excl = excl;
    }
    __syncthreads();

    int pref = s_excl + (incl - s);
#pragma unroll
    for (int u = 0; u < 4; ++u) {
        int i = i0 + u;
        if (i < n) { g_off[i] = pref; g_cur[i] = pref; }
        pref += v[u];
    }
    if (b == nb - 1 && t == 255) g_off[n] = s_excl + total;
}

__global__ void scatter_kernel(const int* __restrict__ ei, int e, int n, int nb) {
    int t = blockIdx.x * blockDim.x + threadIdx.x;
    if (t < nb) g_scan[t] = 0ULL;
    if (t < e) {
        int src = ei[t];
        int dst = ei[e + t];
        int pos = atomicAdd(&g_cur[dst], 1);
        g_csr[pos] = src;
    } else if (t < e + n) {
        int i = t - e;
        int pos = atomicAdd(&g_cur[i], 1);
        g_csr[pos] = i;
    }
}

// ---------------------------------------------------------------------------
// Tensor-core GEMM (HMMA m16n8k16, fp16 in / fp32 accum) + fused alpha.
// TX = input element type (float: convert while staging; __half: raw copy).
// TH = output storage type.
// ---------------------------------------------------------------------------
__device__ __forceinline__ void ldsm_x4(uint32_t a[4], uint32_t addr) {
    asm volatile("ldmatrix.sync.aligned.m8n8.x4.shared.b16 {%0,%1,%2,%3},[%4];"
                 : "=r"(a[0]), "=r"(a[1]), "=r"(a[2]), "=r"(a[3]) : "r"(addr));
}
__device__ __forceinline__ void ldsm_x4_t(uint32_t a[4], uint32_t addr) {
    asm volatile("ldmatrix.sync.aligned.m8n8.x4.trans.shared.b16 {%0,%1,%2,%3},[%4];"
                 : "=r"(a[0]), "=r"(a[1]), "=r"(a[2]), "=r"(a[3]) : "r"(addr));
}
__device__ __forceinline__ void mma16816(float c[4], const uint32_t a[4],
                                         const uint32_t* b) {
    asm volatile(
        "mma.sync.aligned.m16n8k16.row.col.f32.f16.f16.f32 "
        "{%0,%1,%2,%3},{%4,%5,%6,%7},{%8,%9},{%0,%1,%2,%3};"
        : "+f"(c[0]), "+f"(c[1]), "+f"(c[2]), "+f"(c[3])
        : "r"(a[0]), "r"(a[1]), "r"(a[2]), "r"(a[3]), "r"(b[0]), "r"(b[1]));
}

template <int K, int M, typename TX, typename TH>
__device__ __forceinline__ void gemm_mma_body(
    const TX* __restrict__ X, const float* __restrict__ W,
    TH* __restrict__ H,
    const float* __restrict__ a_s, const float* __restrict__ a_d,
    float* __restrict__ as_out, float* __restrict__ ad_out,
    int n, int bid)
{
    constexpr int AP = K + 8;        // halves; AP*2 bytes is 16B-multiple
    constexpr int NP = M + 8;
    constexpr int NT = M / 16;
    constexpr int KS = K / 16;
    __shared__ __half As[64 * AP];
    __shared__ __half Bs[K * NP];
    __shared__ float  sAs[64], sAd[64];

    const int tid = threadIdx.x;
    const int lane = tid & 31;
    const int wid = tid >> 5;
    const int nb = bid * 64;

    if (tid < 64) { sAs[tid] = 0.f; sAd[tid] = 0.f; }

    // Stage A
    if constexpr (sizeof(TX) == 4) {       // fp32 input -> convert
#pragma unroll
        for (int it = 0; it < K / 16; ++it) {
            int idx = tid + it * 256;
            int r = idx / (K / 4);
            int c4 = idx % (K / 4);
            int node = nb + r;
            float4 v = make_float4(0.f, 0.f, 0.f, 0.f);
            if (node < n)
                v = *reinterpret_cast<const float4*>((const float*)X + (size_t)node * K + c4 * 4);
            __half2 h0 = __floats2half2_rn(v.x, v.y);
            __half2 h1 = __floats2half2_rn(v.z, v.w);
            uint2 pk = make_uint2(*(uint32_t*)&h0, *(uint32_t*)&h1);
            *reinterpret_cast<uint2*>(&As[r * AP + c4 * 4]) = pk;
        }
    } else {                               // fp16 input -> raw 16B copies
#pragma unroll
        for (int it = 0; it < K / 32; ++it) {
            int idx = tid + it * 256;
            int r = idx / (K / 8);
            int c8 = idx % (K / 8);
            int node = nb + r;
            uint4 v = make_uint4(0u, 0u, 0u, 0u);
            if (node < n)
                v = *reinterpret_cast<const uint4*>((const __half*)X + (size_t)node * K + c8 * 8);
            *reinterpret_cast<uint4*>(&As[r * AP + c8 * 8]) = v;
        }
    }
    // Stage B (W fp32 -> fp16)
#pragma unroll
    for (int it = 0; it < (K * M / 4) / 256; ++it) {
        int idx = tid + it * 256;
        int r = idx / (M / 4);
        int c4 = idx % (M / 4);
        float4 v = *reinterpret_cast<const float4*>(W + (size_t)r * M + c4 * 4);
        __half2 h0 = __floats2half2_rn(v.x, v.y);
        __half2 h1 = __floats2half2_rn(v.z, v.w);
        uint2 pk = make_uint2(*(uint32_t*)&h0, *(uint32_t*)&h1);
        *reinterpret_cast<uint2*>(&Bs[r * NP + c4 * 4]) = pk;
    }
    __syncthreads();

    const int r0 = (wid >> 1) * 16;
    const int n0 = (wid & 1) * (M == 64 ? 32 : 16);

    float c[NT][4];
#pragma unroll
    for (int t2 = 0; t2 < NT; ++t2)
#pragma unroll
        for (int u = 0; u < 4; ++u) c[t2][u] = 0.f;

    const uint32_t aBase = (uint32_t)__cvta_generic_to_shared(As);
    const uint32_t bBase = (uint32_t)__cvta_generic_to_shared(Bs);

#pragma unroll
    for (int kk = 0; kk < KS; ++kk) {
        int k0 = kk * 16;
        uint32_t a[4];
        ldsm_x4(a, aBase + ((r0 + (lane & 15)) * AP + k0 + ((lane >> 4) << 3)) * 2);
#pragma unroll
        for (int tp = 0; tp < NT / 2; ++tp) {
            int ncol = n0 + tp * 16;
            int row = k0 + ((lane >> 3) & 1) * 8 + (lane & 7);
            int col = ncol + (lane >> 4) * 8;
            uint32_t bb[4];
            ldsm_x4_t(bb, bBase + (row * NP + col) * 2);
            mma16816(c[tp * 2], a, bb);
            mma16816(c[tp * 2 + 1], a, bb + 2);
        }
    }

    const int group = lane >> 2;
    const int qt = lane & 3;
    const int rlo = r0 + group, rhi = rlo + 8;
    const int nlo = nb + rlo, nhi = nb + rhi;
    float slo = 0.f, dlo = 0.f, shi = 0.f, dhi = 0.f;
#pragma unroll
    for (int t2 = 0; t2 < NT; ++t2) {
        int c0 = n0 + t2 * 8 + qt * 2;
        float as0 = a_s[c0], as1 = a_s[c0 + 1];
        float ad0 = a_d[c0], ad1 = a_d[c0 + 1];
        slo += c[t2][0] * as0 + c[t2][1] * as1;
        dlo += c[t2][0] * ad0 + c[t2][1] * ad1;
        shi += c[t2][2] * as0 + c[t2][3] * as1;
        dhi += c[t2][2] * ad0 + c[t2][3] * ad1;
        if (nlo < n) {
            if constexpr (sizeof(TH) == 2) {
                __half2 h = __floats2half2_rn(c[t2][0], c[t2][1]);
                *reinterpret_cast<__half2*>((__half*)H + (size_t)nlo * M + c0) = h;
            } else {
                *reinterpret_cast<float2*>((float*)H + (size_t)nlo * M + c0) =
                    make_float2(c[t2][0], c[t2][1]);
            }
        }
        if (nhi < n) {
            if constexpr (sizeof(TH) == 2) {
                __half2 h = __floats2half2_rn(c[t2][2], c[t2][3]);
                *reinterpret_cast<__half2*>((__half*)H + (size_t)nhi * M + c0) = h;
            } else {
                *reinterpret_cast<float2*>((float*)H + (size_t)nhi * M + c0) =
                    make_float2(c[t2][2], c[t2][3]);
            }
        }
    }
#pragma unroll
    for (int o = 1; o <= 2; o <<= 1) {
        slo += __shfl_xor_sync(0xffffffffu, slo, o);
        dlo += __shfl_xor_sync(0xffffffffu, dlo, o);
        shi += __shfl_xor_sync(0xffffffffu, shi, o);
        dhi += __shfl_xor_sync(0xffffffffu, dhi, o);
    }
    if (qt == 0) {
        atomicAdd(&sAs[rlo], slo);
        atomicAdd(&sAd[rlo], dlo);
        atomicAdd(&sAs[rhi], shi);
        atomicAdd(&sAd[rhi], dhi);
    }
    __syncthreads();
    if (tid < 64) {
        int node = nb + tid;
        if (node < n) { as_out[node] = sAs[tid]; ad_out[node] = sAd[tid]; }
    }
}

__global__ void __launch_bounds__(256) fused_gemm1_hist_kernel(
    const float* __restrict__ X, const float* __restrict__ W1,
    const float* __restrict__ aS1, const float* __restrict__ aD1,
    const int* __restrict__ ei, int n, int e, int gemm_blocks)
{
    if ((int)blockIdx.x < gemm_blocks) {
        gemm_mma_body<128, 64, float, __half>(X, W1, g_h1h, aS1, aD1,
                                              g_as1, g_ad1, n, blockIdx.x);
    } else {
        int hb = gridDim.x - gemm_blocks;
        for (int t = (blockIdx.x - gemm_blocks) * 256 + threadIdx.x; t < e;
             t += hb * 256) {
            int dst = ei[e + t];
            atomicAdd(&g_deg[dst], 1);
        }
    }
}

__global__ void __launch_bounds__(256) gemm2_kernel(
    const float* __restrict__ W2,
    const float* __restrict__ aS2, const float* __restrict__ aD2, int n)
{
    gemm_mma_body<64, 32, __half, float>(g_o1h, W2, g_h2, aS2, aD2,
                                         g_as2, g_ad2, n, blockIdx.x);
}

// ---------------------------------------------------------------------------
// Gather layer 1 (R8 layout): warp per node, smem-staged weights; output
// stored directly as fp16 (identical values to the previous fp32->fp16
// conversion done later in gemm2 staging — zero added error).
// ---------------------------------------------------------------------------
__global__ void __launch_bounds__(256) gather64_kernel(
    const float* __restrict__ b, int n)
{
    __shared__ float2 stage[8][32];
    int node = (blockIdx.x * blockDim.x + threadIdx.x) >> 5;
    int lane = threadIdx.x & 31;
    int wid = (threadIdx.x >> 5) & 7;
    if (node >= n) return;
    int p0 = g_off[node], p1 = g_off[node + 1];
    float advl = g_ad1[node];
    const __half2* hb = reinterpret_cast<const __half2*>(g_h1h) + lane;
    float sum = 0.f, a0 = 0.f, a1 = 0.f;

    for (int base = p0; base < p1; base += 32) {
        int p = base + lane;
        int src = 0;
        float w = 0.f;
        if (p < p1) {
            src = g_csr[p];
            float ev = g_as1[src] + advl;
            ev = ev > 0.f ? ev : 0.2f * ev;
            w = __expf(ev);
        }
        sum += w;
        stage[wid][lane] = make_float2(w, __int_as_float(src * 32));
        __syncwarp();
        int nc = min(32, p1 - base);
#pragma unroll 4
        for (int j = 0; j < nc; ++j) {
            float2 sj = stage[wid][j];
            float2 hv = __half22float2(hb[__float_as_int(sj.y)]);
            a0 = fmaf(sj.x, hv.x, a0);
            a1 = fmaf(sj.x, hv.y, a1);
        }
        __syncwarp();
    }
#pragma unroll
    for (int o = 16; o; o >>= 1) sum += __shfl_xor_sync(0xffffffffu, sum, o);
    float inv = 1.f / (sum + 1e-16f);
    float ox = fmaxf(fmaf(a0, inv, b[lane * 2]), 0.f);
    float oy = fmaxf(fmaf(a1, inv, b[lane * 2 + 1]), 0.f);
    *reinterpret_cast<__half2*>(g_o1h + (size_t)node * 64 + lane * 2) =
        __floats2half2_rn(ox, oy);
}

// ---------------------------------------------------------------------------
// Gather layer 2 + fused log_softmax (R8 layout).
// ---------------------------------------------------------------------------
__global__ void __launch_bounds__(256) gather32_kernel(
    const float* __restrict__ b, float* __restrict__ out, int n)
{
    __shared__ float2 stage[8][32];
    int node = (blockIdx.x * blockDim.x + threadIdx.x) >> 5;
    int lane = threadIdx.x & 31;
    int wid = (threadIdx.x >> 5) & 7;
    if (node >= n) return;
    int p0 = g_off[node], p1 = g_off[node + 1];
    float advl = g_ad2[node];
    const float* hb = g_h2 + lane;
    float sum = 0.f, acc = 0.f;

    for (int base = p0; base < p1; base += 32) {
        int p = base + lane;
        int src = 0;
        float w = 0.f;
        if (p < p1) {
            src = g_csr[p];
            float ev = g_as2[src] + advl;
            ev = ev > 0.f ? ev : 0.2f * ev;
            w = __expf(ev);
        }
        sum += w;
        stage[wid][lane] = make_float2(w, __int_as_float(src * 32));
        __syncwarp();
        int nc = min(32, p1 - base);
#pragma unroll 4
        for (int j = 0; j < nc; ++j) {
            float2 sj = stage[wid][j];
            acc = fmaf(sj.x, hb[__float_as_int(sj.y)], acc);
        }
        __syncwarp();
    }
#pragma unroll
    for (int o = 16; o; o >>= 1) sum += __shfl_xor_sync(0xffffffffu, sum, o);

    float v = fmaf(acc, 1.f / (sum + 1e-16f), b[lane]);
    float m = v;
#pragma unroll
    for (int o = 16; o; o >>= 1) m = fmaxf(m, __shfl_xor_sync(0xffffffffu, m, o));
    float ex = __expf(v - m);
    float s2 = ex;
#pragma unroll
    for (int o = 16; o; o >>= 1) s2 += __shfl_xor_sync(0xffffffffu, s2, o);
    out[(size_t)node * 32 + lane] = v - m - __logf(s2);
}

// ---------------------------------------------------------------------------
// Launch: 6 kernels, no runtime API calls.
// ---------------------------------------------------------------------------
extern "C" void kernel_launch(void* const* d_in, const int* in_sizes, int n_in,
                              void* d_out, int out_size) {
    const float* x   = (const float*)d_in[0];
    const int*   ei  = (const int*)d_in[1];     // int64 coerced to int32 by harness
    const float* W1  = (const float*)d_in[2];
    const float* aS1 = (const float*)d_in[3];
    const float* aD1 = (const float*)d_in[4];
    const float* b1  = (const float*)d_in[5];
    const float* W2  = (const float*)d_in[6];
    const float* aS2 = (const float*)d_in[7];
    const float* aD2 = (const float*)d_in[8];
    const float* b2  = (const float*)d_in[9];
    float* out = (float*)d_out;

    const int n = in_sizes[0] / 128;
    const int e = in_sizes[1] / 2;
    const int etot = e + n;
    const int nb = (n + SCAN_CHUNK - 1) / SCAN_CHUNK;
    const int gemm1_blocks = (n + 63) / 64;

    fused_gemm1_hist_kernel<<<gemm1_blocks + HIST_BLOCKS, 256>>>(
        x, W1, aS1, aD1, ei, n, e, gemm1_blocks);

    scan_onepass_kernel<<<nb, 256>>>(n, nb);
    scatter_kernel<<<(etot + 255) / 256, 256>>>(ei, e, n, nb);

    gather64_kernel<<<(n * 32 + 255) / 256, 256>>>(b1, n);

    gemm2_kernel<<<(n + 63) / 64, 256>>>(W2, aS2, aD2, n);
    gather32_kernel<<<(n * 32 + 255) / 256, 256>>>(b2, out, n);
}